// round 16
// baseline (speedup 1.0000x reference)
#include <cuda_runtime.h>
#include <cuda_fp16.h>
#include <math.h>
#include <stdint.h>

// ===========================================================================
// Problem constants
// ===========================================================================
#define B_ROWS 32768
#define IN_DIM 128
#define HDIM   2048
#define DOUT   1536
#define NBINS  8
#define MIN_W  0.001f
#define MIN_H  0.001f
#define MIN_D  0.001f
#define INV_BN 0.9999950000374997f

// Scratch (__device__ globals: allocation-free rule)
__device__ __half  g_h1[(size_t)B_ROWS * HDIM];
__device__ __half  g_h2[(size_t)B_ROWS * HDIM];
__device__ float   g_params[(size_t)B_ROWS * DOUT];
__device__ __half  g_xe [(size_t)B_ROWS * 64];          // even cols of x, fp16
__device__ uint32_t g_w1p[(size_t)32   * HDIM];         // W1 k-pair packed [K/2][N]
__device__ uint32_t g_w2p[(size_t)1024 * HDIM];         // W2 packed
__device__ uint32_t g_w3p[(size_t)1024 * DOUT];         // W3 packed

__device__ __forceinline__ void mma_f16(float* d, const uint32_t* a, const uint32_t* b) {
    asm volatile(
        "mma.sync.aligned.m16n8k16.row.col.f32.f16.f16.f32 "
        "{%0,%1,%2,%3}, {%4,%5,%6,%7}, {%8,%9}, {%0,%1,%2,%3};"
        : "+f"(d[0]), "+f"(d[1]), "+f"(d[2]), "+f"(d[3])
        : "r"(a[0]), "r"(a[1]), "r"(a[2]), "r"(a[3]), "r"(b[0]), "r"(b[1]));
}

__device__ __forceinline__ void ldmatrix_x4(uint32_t* r, uint32_t saddr) {
    asm volatile("ldmatrix.sync.aligned.m8n8.x4.shared.b16 {%0,%1,%2,%3}, [%4];"
        : "=r"(r[0]), "=r"(r[1]), "=r"(r[2]), "=r"(r[3]) : "r"(saddr));
}

__device__ __forceinline__ void cp_async16(uint32_t saddr, const void* gptr) {
    asm volatile("cp.async.cg.shared.global [%0], [%1], 16;" :: "r"(saddr), "l"(gptr));
}
#define CP_COMMIT() asm volatile("cp.async.commit_group;" ::: "memory")
// All groups older than the newest 1 are guaranteed complete after this.
#define CP_WAIT1()  asm volatile("cp.async.wait_group 1;" ::: "memory")

// ===========================================================================
// fp16 mma.sync GEMM: C[M x N] = epilogue(A[M x K] @ W[K x N] + bias)
//   Block tile 128 x 128, K-chunk 64, 3-stage cp.async, 512 threads,
//   2 CTAs/SM (8 warps/SMSP for latency hiding).
//   16 warps 4(M) x 4(N); warp tile 32 x 32 = 2x4 m16n8k16 tiles.
//   SMEM (32-bit words): Asw[128][36] (m-major k-pair words, pad 4)
//                        Bsw[32][136] (kpair-major packed {W[2k],W[2k+1]})
//   A frags via ldmatrix.x4; B frag word bank = (8c + g) -> conflict-free.
//   Single __syncthreads per chunk (slot reuse at distance N_STAGES-1):
//     iter i: wait_group(1) [group i done] -> sync -> issue slot (i+2)%3
//     -> compute slot i%3.
//   EPI 0: half( gamma*relu(z+bias)*INV_BN + beta )   -> __half C
//   EPI 1: z + bias                                   -> float C
// ===========================================================================
#define A_LDW  36
#define B_LDW  136
#define A_WORDS (128 * A_LDW)              // 4608
#define B_WORDS (32 * B_LDW)               // 4352
#define STAGE_WORDS (A_WORDS + B_WORDS)    // 8960
#define N_STAGES 3
#define SMEM_BYTES  (N_STAGES * STAGE_WORDS * 4)  // 107520 B per CTA
#define NTHREADS 512

template <int EPI>
__global__ void __launch_bounds__(NTHREADS, 2) mma_gemm_h(
    const __half* __restrict__ A, int lda,          // lda in halves
    const uint32_t* __restrict__ Wp, int ldbw,      // packed words per row
    void* __restrict__ Cv, int ldc, int K,
    const float* __restrict__ bias,
    const float* __restrict__ gamma,
    const float* __restrict__ beta)
{
    extern __shared__ uint32_t smw[];
    const int tid = threadIdx.x;
    const int wid = tid >> 5;
    const int lane = tid & 31;
    const int g = lane >> 2;           // 0..7
    const int c = lane & 3;            // 0..3
    const int wm = wid >> 2;           // 0..3 -> 32 rows each
    const int wn = wid & 3;            // 0..3 -> 32 cols each
    const int row0 = blockIdx.y * 128;
    const int col0 = blockIdx.x * 128;
    const int NK = K / 64;

    // cp.async staging (512 threads: 2 A-lines + 2 B-lines each)
    const int am  = tid >> 3;          // A row 0..63 (x2 -> 128)
    const int akc = (tid & 7) * 4;     // A word-chunk (4 words = 8 halves)
    const int bkp = tid >> 5;          // B kpair-row 0..15 (x2 -> 32)
    const int bnc = (tid & 31) * 4;    // B word-chunk 0..124

    // ldmatrix lane mapping
    const int lq = lane >> 3, lr = lane & 7;
    const int lm_off = ((lq & 1) * 8 + lr) * A_LDW + (lq >> 1) * 4;  // words

    uint32_t smem_u32;
    {
        uint64_t t = __cvta_generic_to_shared(smw);
        smem_u32 = (uint32_t)t;
    }

    float acc[2][4][4];
#pragma unroll
    for (int i = 0; i < 2; ++i)
#pragma unroll
        for (int j = 0; j < 4; ++j)
#pragma unroll
            for (int q = 0; q < 4; ++q) acc[i][j][q] = 0.0f;

    auto issue_stage = [&](int s, int kt) {            // kt in k-halves
        const uint32_t abase = smem_u32 + (uint32_t)(s * STAGE_WORDS) * 4u;
        const uint32_t bbase = abase + A_WORDS * 4u;
#pragma unroll
        for (int it = 0; it < 2; ++it) {
            const int m = am + it * 64;
            cp_async16(abase + (uint32_t)(m * A_LDW + akc) * 4u,
                       A + (size_t)(row0 + m) * lda + kt + akc * 2);
        }
#pragma unroll
        for (int it = 0; it < 2; ++it) {
            const int kp = bkp + it * 16;
            cp_async16(bbase + (uint32_t)(kp * B_LDW + bnc) * 4u,
                       Wp + (size_t)(kt / 2 + kp) * ldbw + col0 + bnc);
        }
    };

    // prologue: prefetch slots 0,1 (commit always for group accounting)
#pragma unroll
    for (int j = 0; j < N_STAGES - 1; ++j) {
        if (j < NK) issue_stage(j, j * 64);
        CP_COMMIT();
    }

    for (int i = 0; i < NK; ++i) {
        CP_WAIT1();            // group i complete (only group i+1 may pend)
        __syncthreads();       // consumers of slot (i-1)%3 are done

        if (i + N_STAGES - 1 < NK)
            issue_stage((i + N_STAGES - 1) % N_STAGES, (i + N_STAGES - 1) * 64);
        CP_COMMIT();

        const int s = i % N_STAGES;
        const uint32_t a_stage = smem_u32 + (uint32_t)(s * STAGE_WORDS) * 4u;
        const uint32_t* Bsw = smw + s * STAGE_WORDS + A_WORDS;   // [32][136]

#pragma unroll
        for (int ksw = 0; ksw < 32; ksw += 8) {                  // 4 ksteps of k16
            uint32_t af[2][4], bf[4][2];
#pragma unroll
            for (int mt = 0; mt < 2; ++mt) {
                const int rb = wm * 32 + mt * 16;
                ldmatrix_x4(af[mt],
                            a_stage + (uint32_t)(rb * A_LDW + ksw + lm_off) * 4u);
            }
#pragma unroll
            for (int nt = 0; nt < 4; ++nt) {
                const int nb = wn * 32 + nt * 8;
                bf[nt][0] = Bsw[(ksw + c)     * B_LDW + nb + g];
                bf[nt][1] = Bsw[(ksw + c + 4) * B_LDW + nb + g];
            }
#pragma unroll
            for (int mt = 0; mt < 2; ++mt)
#pragma unroll
                for (int nt = 0; nt < 4; ++nt)
                    mma_f16(acc[mt][nt], af[mt], bf[nt]);
        }
    }

    // ---- epilogue ----
#pragma unroll
    for (int mt = 0; mt < 2; ++mt) {
        const int r0 = row0 + wm * 32 + mt * 16 + g;
#pragma unroll
        for (int nt = 0; nt < 4; ++nt) {
            const int cb = col0 + wn * 32 + nt * 8 + 2 * c;
            float z[4];
            z[0] = acc[mt][nt][0] + __ldg(&bias[cb]);
            z[1] = acc[mt][nt][1] + __ldg(&bias[cb + 1]);
            z[2] = acc[mt][nt][2] + __ldg(&bias[cb]);
            z[3] = acc[mt][nt][3] + __ldg(&bias[cb + 1]);
            if (EPI == 0) {
                const float ga0 = __ldg(&gamma[cb]),     be0  = __ldg(&beta[cb]);
                const float ga1 = __ldg(&gamma[cb + 1]), be1v = __ldg(&beta[cb + 1]);
                z[0] = ga0 * fmaxf(z[0], 0.0f) * INV_BN + be0;
                z[1] = ga1 * fmaxf(z[1], 0.0f) * INV_BN + be1v;
                z[2] = ga0 * fmaxf(z[2], 0.0f) * INV_BN + be0;
                z[3] = ga1 * fmaxf(z[3], 0.0f) * INV_BN + be1v;
                __half* C = (__half*)Cv;
                *(__half2*)&C[(size_t)r0 * ldc + cb]       = __floats2half2_rn(z[0], z[1]);
                *(__half2*)&C[(size_t)(r0 + 8) * ldc + cb] = __floats2half2_rn(z[2], z[3]);
            } else {
                float* C = (float*)Cv;
                *(float2*)&C[(size_t)r0 * ldc + cb]       = make_float2(z[0], z[1]);
                *(float2*)&C[(size_t)(r0 + 8) * ldc + cb] = make_float2(z[2], z[3]);
            }
        }
    }
}

// ===========================================================================
// Prep kernels (R10 structure: separate launches)
// ===========================================================================
__global__ void pack_x_kernel(const float* __restrict__ x, __half* __restrict__ xe)
{
    const int i = blockIdx.x * 256 + threadIdx.x;   // over B_ROWS*64
    const int row = i >> 6, j = i & 63;
    xe[i] = __float2half_rn(x[(size_t)row * IN_DIM + 2 * j]);
}

// pack W[K][N] fp32 -> [K/2][N] uint32 words {h(W[2kp][n]), h(W[2kp+1][n])}
__global__ void pack_w_kernel(const float* __restrict__ W, uint32_t* __restrict__ out,
                              int K2, int N)
{
    const int i = blockIdx.x * 256 + threadIdx.x;
    if (i >= K2 * N) return;
    const int kp = i / N, n = i - kp * N;
    const __half lo = __float2half_rn(W[(size_t)(2 * kp) * N + n]);
    const __half hi = __float2half_rn(W[(size_t)(2 * kp + 1) * N + n]);
    out[i] = (uint32_t)__half_as_ushort(lo) | ((uint32_t)__half_as_ushort(hi) << 16);
}

// ===========================================================================
// RQ-spline + scatter epilogue
// ===========================================================================
__global__ __launch_bounds__(256) void spline_kernel(
    const float* __restrict__ x,
    const float* __restrict__ params,
    float* __restrict__ out,
    float* __restrict__ logdet)
{
    const int tid = threadIdx.x;
    const int row = blockIdx.x * 4 + (tid >> 6);
    const int j = tid & 63;
    const float* p = params + (size_t)row * DOUT + j * 24;

    float wr[NBINS], hr[NBINS], drw[NBINS];
#pragma unroll
    for (int k = 0; k < NBINS; ++k) wr[k] = p[k];
#pragma unroll
    for (int k = 0; k < NBINS; ++k) hr[k] = p[NBINS + k];
#pragma unroll
    for (int k = 0; k < NBINS; ++k) drw[k] = p[2 * NBINS + k];

    const float xi = x[(size_t)row * IN_DIM + 2 * j + 1];
    const float xt = x[(size_t)row * IN_DIM + 2 * j];

    float cw[NBINS + 1], ch[NBINS + 1], dd[NBINS + 1];
    {
        float m = wr[0];
#pragma unroll
        for (int k = 1; k < NBINS; ++k) m = fmaxf(m, wr[k]);
        float e[NBINS], s = 0.0f;
#pragma unroll
        for (int k = 0; k < NBINS; ++k) { e[k] = expf(wr[k] - m); s += e[k]; }
        const float inv = 1.0f / s;
        cw[0] = 0.0f;
#pragma unroll
        for (int k = 0; k < NBINS; ++k)
            cw[k + 1] = cw[k] + (MIN_W + (1.0f - MIN_W * NBINS) * e[k] * inv);
    }
    {
        float m = hr[0];
#pragma unroll
        for (int k = 1; k < NBINS; ++k) m = fmaxf(m, hr[k]);
        float e[NBINS], s = 0.0f;
#pragma unroll
        for (int k = 0; k < NBINS; ++k) { e[k] = expf(hr[k] - m); s += e[k]; }
        const float inv = 1.0f / s;
        ch[0] = 0.0f;
#pragma unroll
        for (int k = 0; k < NBINS; ++k)
            ch[k + 1] = ch[k] + (MIN_H + (1.0f - MIN_H * NBINS) * e[k] * inv);
    }
#pragma unroll
    for (int k = 0; k < NBINS; ++k) {
        const float v = drw[k];
        dd[k] = MIN_D + (fmaxf(v, 0.0f) + log1pf(expf(-fabsf(v))));
    }
    dd[NBINS] = MIN_D;

    int bin = 0;
#pragma unroll
    for (int k = 0; k < NBINS; ++k) bin += (xi > cw[k]) ? 1 : 0;
    bin = min(max(bin, 0), NBINS - 1);

    const float xl = cw[bin], xr = cw[bin + 1];
    const float yl = ch[bin], yr = ch[bin + 1];
    const float bw = xr - xl, bh = yr - yl;
    const float dl = dd[bin], dr = dd[bin + 1];

    float t = (xi - xl) / bw;
    t = fminf(fmaxf(t, 0.0f), 1.0f);

    const float num = bh * (dl * t * t + 2.0f * t * (1.0f - t));
    const float den = dl + (dr - dl) * t;
    const float yv = yl + num / den;
    const float ld = logf(bh) + 2.0f * logf(2.0f * t * (1.0f - t) * dr + dl) - logf(den);

    out[(size_t)row * IN_DIM + 2 * j] = xt;
    out[(size_t)row * IN_DIM + 2 * j + 1] = yv;

    __shared__ float red[256];
    red[tid] = ld;
    __syncthreads();
    for (int s = 32; s > 0; s >>= 1) {
        if ((tid & 63) < s) red[tid] += red[tid + s];
        __syncthreads();
    }
    if ((tid & 63) == 0) logdet[row] = red[tid];
}

// ===========================================================================
// Host side
// ===========================================================================
extern "C" void kernel_launch(void* const* d_in, const int* in_sizes, int n_in,
                              void* d_out, int out_size)
{
    const float* x   = (const float*)d_in[0];
    const float* W1  = (const float*)d_in[1];
    const float* b1  = (const float*)d_in[2];
    const float* g1  = (const float*)d_in[3];
    const float* be1 = (const float*)d_in[4];
    const float* W2  = (const float*)d_in[5];
    const float* b2  = (const float*)d_in[6];
    const float* g2  = (const float*)d_in[7];
    const float* be2 = (const float*)d_in[8];
    const float* W3  = (const float*)d_in[9];
    const float* b3  = (const float*)d_in[10];

    float* out    = (float*)d_out;
    float* logdet = out + (size_t)B_ROWS * IN_DIM;

    __half *h1, *h2, *xe;
    float *pp;
    uint32_t *w1p, *w2p, *w3p;
    cudaGetSymbolAddress((void**)&h1,  g_h1);
    cudaGetSymbolAddress((void**)&h2,  g_h2);
    cudaGetSymbolAddress((void**)&pp,  g_params);
    cudaGetSymbolAddress((void**)&xe,  g_xe);
    cudaGetSymbolAddress((void**)&w1p, g_w1p);
    cudaGetSymbolAddress((void**)&w2p, g_w2p);
    cudaGetSymbolAddress((void**)&w3p, g_w3p);

    cudaFuncSetAttribute(mma_gemm_h<0>, cudaFuncAttributeMaxDynamicSharedMemorySize, SMEM_BYTES);
    cudaFuncSetAttribute(mma_gemm_h<1>, cudaFuncAttributeMaxDynamicSharedMemorySize, SMEM_BYTES);

    // Prep: pack x even cols + k-pair-interleave weights (all fp16)
    pack_x_kernel<<<(B_ROWS * 64) / 256, 256>>>(x, xe);
    pack_w_kernel<<<(32   * HDIM + 255) / 256, 256>>>(W1, w1p, 32,   HDIM);
    pack_w_kernel<<<(1024 * HDIM + 255) / 256, 256>>>(W2, w2p, 1024, HDIM);
    pack_w_kernel<<<(1024 * DOUT + 255) / 256, 256>>>(W3, w3p, 1024, DOUT);

    // GEMM1: [32768 x 64] @ [64 x 2048] -> h1 (fp16)
    mma_gemm_h<0><<<dim3(HDIM / 128, B_ROWS / 128), NTHREADS, SMEM_BYTES>>>(
        xe, 64, w1p, HDIM, h1, HDIM, 64, b1, g1, be1);
    // GEMM2: [32768 x 2048] @ [2048 x 2048] -> h2 (fp16)
    mma_gemm_h<0><<<dim3(HDIM / 128, B_ROWS / 128), NTHREADS, SMEM_BYTES>>>(
        h1, HDIM, w2p, HDIM, h2, HDIM, HDIM, b2, g2, be2);
    // GEMM3: [32768 x 2048] @ [2048 x 1536] -> params (fp32)
    mma_gemm_h<1><<<dim3(DOUT / 128, B_ROWS / 128), NTHREADS, SMEM_BYTES>>>(
        h2, HDIM, w3p, DOUT, pp, DOUT, HDIM, b3, (const float*)0, (const float*)0);

    // Spline + scatter + log_det
    spline_kernel<<<B_ROWS / 4, 256>>>(x, pp, out, logdet);
}

// round 17
// speedup vs baseline: 1.0734x; 1.0734x over previous
#include <cuda_runtime.h>
#include <cuda_fp16.h>
#include <math.h>
#include <stdint.h>

// ===========================================================================
// Problem constants
// ===========================================================================
#define B_ROWS 32768
#define IN_DIM 128
#define HDIM   2048
#define DOUT   1536
#define NBINS  8
#define MIN_W  0.001f
#define MIN_H  0.001f
#define MIN_D  0.001f
#define INV_BN 0.9999950000374997f

// Scratch (__device__ globals: allocation-free rule)
__device__ __half  g_h1[(size_t)B_ROWS * HDIM];
__device__ __half  g_h2[(size_t)B_ROWS * HDIM];
__device__ float   g_params[(size_t)B_ROWS * DOUT];
__device__ __half  g_xe [(size_t)B_ROWS * 64];          // even cols of x, fp16
// Weights packed n-major: wp[n][kp] = {h(W[2kp][n]), h(W[2kp+1][n])}
__device__ uint32_t g_w1p[(size_t)HDIM * 32];
__device__ uint32_t g_w2p[(size_t)HDIM * 1024];
__device__ uint32_t g_w3p[(size_t)DOUT * 1024];

__device__ __forceinline__ void mma_f16(float* d, const uint32_t* a, const uint32_t* b) {
    asm volatile(
        "mma.sync.aligned.m16n8k16.row.col.f32.f16.f16.f32 "
        "{%0,%1,%2,%3}, {%4,%5,%6,%7}, {%8,%9}, {%0,%1,%2,%3};"
        : "+f"(d[0]), "+f"(d[1]), "+f"(d[2]), "+f"(d[3])
        : "r"(a[0]), "r"(a[1]), "r"(a[2]), "r"(a[3]), "r"(b[0]), "r"(b[1]));
}

__device__ __forceinline__ void ldmatrix_x4(uint32_t* r, uint32_t saddr) {
    asm volatile("ldmatrix.sync.aligned.m8n8.x4.shared.b16 {%0,%1,%2,%3}, [%4];"
        : "=r"(r[0]), "=r"(r[1]), "=r"(r[2]), "=r"(r[3]) : "r"(saddr));
}

__device__ __forceinline__ void cp_async16(uint32_t saddr, const void* gptr) {
    asm volatile("cp.async.cg.shared.global [%0], [%1], 16;" :: "r"(saddr), "l"(gptr));
}
#define CP_COMMIT() asm volatile("cp.async.commit_group;" ::: "memory")
// All groups older than the newest 1 are guaranteed complete after this.
#define CP_WAIT1()  asm volatile("cp.async.wait_group 1;" ::: "memory")

// ===========================================================================
// fp16 mma.sync GEMM: C[M x N] = epilogue(A[M x K] @ W[K x N] + bias)
//   Block tile 128 x 128, K-chunk 64, 3-stage cp.async, 256 threads,
//   2 CTAs/SM. 8 warps 2(M) x 4(N); warp tile 64 x 32 = 4x4 m16n8k16 tiles.
//   SMEM (32-bit words): Asw[128][36] (m-major k-pair words, pad 4)
//                        Bsw[128][36] (n-major: row n, 32 kpair words, pad 4)
//   A and B frags BOTH via ldmatrix.x4 (rows stride 36 words -> banks 4r,
//   conflict-free). B lane (g,c) <- word (kp=ksw+c, n=nb+g): identical data
//   words as the previous LDS path.
//   Single __syncthreads per chunk (slot reuse at distance N_STAGES-1).
//   EPI 0: half( gamma*relu(z+bias)*INV_BN + beta )   -> __half C
//   EPI 1: z + bias                                   -> float C
// ===========================================================================
#define A_LDW  36
#define B_LDW  36
#define A_WORDS (128 * A_LDW)              // 4608
#define B_WORDS (128 * B_LDW)              // 4608
#define STAGE_WORDS (A_WORDS + B_WORDS)    // 9216
#define N_STAGES 3
#define SMEM_BYTES  (N_STAGES * STAGE_WORDS * 4)  // 110592 B per CTA

template <int EPI>
__global__ void __launch_bounds__(256, 2) mma_gemm_h(
    const __half* __restrict__ A, int lda,          // lda in halves
    const uint32_t* __restrict__ Wp, int ldbw,      // = K/2 (words per n-row)
    void* __restrict__ Cv, int ldc, int K,
    const float* __restrict__ bias,
    const float* __restrict__ gamma,
    const float* __restrict__ beta)
{
    extern __shared__ uint32_t smw[];
    const int tid = threadIdx.x;
    const int wid = tid >> 5;
    const int lane = tid & 31;
    const int g = lane >> 2;           // 0..7
    const int c = lane & 3;            // 0..3
    const int wm = wid >> 2;           // 0..1 -> 64 rows
    const int wn = wid & 3;            // 0..3 -> 32 cols
    const int row0 = blockIdx.y * 128;
    const int col0 = blockIdx.x * 128;
    const int NK = K / 64;

    // cp.async staging: same index pattern for A and B (both 128 x 32-word)
    const int sm_r = tid >> 3;         // row 0..31 (x4 -> 128)
    const int sm_q = (tid & 7) * 4;    // word quad 0..28

    // ldmatrix lane mapping for A (m-major)
    const int lq = lane >> 3, lr = lane & 7;
    const int lm_off = ((lq & 1) * 8 + lr) * A_LDW + (lq >> 1) * 4;  // words

    // ldmatrix lane mapping for B (n-major): x4 = {nt lo, nt hi, nt+1 lo, nt+1 hi}
    const int b_row = ((lane >> 4) & 1) * 8 + (lane & 7);   // row within 16-n block
    const int b_col = ((lane >> 3) & 1) * 4;                // +0 (lo k) / +4 (hi k)

    uint32_t smem_u32;
    {
        uint64_t t = __cvta_generic_to_shared(smw);
        smem_u32 = (uint32_t)t;
    }

    float acc[4][4][4];
#pragma unroll
    for (int i = 0; i < 4; ++i)
#pragma unroll
        for (int j = 0; j < 4; ++j)
#pragma unroll
            for (int q = 0; q < 4; ++q) acc[i][j][q] = 0.0f;

    auto issue_stage = [&](int s, int kt) {            // kt in k-halves
        const int kt2 = kt >> 1;                       // kpair offset
        const uint32_t abase = smem_u32 + (uint32_t)(s * STAGE_WORDS) * 4u;
        const uint32_t bbase = abase + A_WORDS * 4u;
#pragma unroll
        for (int it = 0; it < 4; ++it) {
            const int m = sm_r + it * 32;
            cp_async16(abase + (uint32_t)(m * A_LDW + sm_q) * 4u,
                       A + (size_t)(row0 + m) * lda + kt + sm_q * 2);
        }
#pragma unroll
        for (int it = 0; it < 4; ++it) {
            const int n = sm_r + it * 32;
            cp_async16(bbase + (uint32_t)(n * B_LDW + sm_q) * 4u,
                       Wp + (size_t)(col0 + n) * ldbw + kt2 + sm_q);
        }
    };

    // prologue: prefetch slots 0,1 (commit always for group accounting)
#pragma unroll
    for (int j = 0; j < N_STAGES - 1; ++j) {
        if (j < NK) issue_stage(j, j * 64);
        CP_COMMIT();
    }

    for (int i = 0; i < NK; ++i) {
        CP_WAIT1();            // group i complete (only group i+1 may pend)
        __syncthreads();       // consumers of slot (i-1)%3 are done

        if (i + N_STAGES - 1 < NK)
            issue_stage((i + N_STAGES - 1) % N_STAGES, (i + N_STAGES - 1) * 64);
        CP_COMMIT();

        const int s = i % N_STAGES;
        const uint32_t a_stage = smem_u32 + (uint32_t)(s * STAGE_WORDS) * 4u;
        const uint32_t b_stage = a_stage + A_WORDS * 4u;

#pragma unroll
        for (int ksw = 0; ksw < 32; ksw += 8) {                  // 4 ksteps of k16
            uint32_t af[4][4], bf0[4], bf1[4];
#pragma unroll
            for (int mt = 0; mt < 4; ++mt) {
                const int rb = wm * 64 + mt * 16;
                ldmatrix_x4(af[mt],
                            a_stage + (uint32_t)(rb * A_LDW + ksw + lm_off) * 4u);
            }
            {
                const int nb = wn * 32;
                ldmatrix_x4(bf0, b_stage +
                    (uint32_t)((nb + b_row) * B_LDW + ksw + b_col) * 4u);
                ldmatrix_x4(bf1, b_stage +
                    (uint32_t)((nb + 16 + b_row) * B_LDW + ksw + b_col) * 4u);
            }
            // bf0 = {nt0.lo, nt0.hi, nt1.lo, nt1.hi}; bf1 = nt2, nt3
#pragma unroll
            for (int mt = 0; mt < 4; ++mt) {
                mma_f16(acc[mt][0], af[mt], bf0 + 0);
                mma_f16(acc[mt][1], af[mt], bf0 + 2);
                mma_f16(acc[mt][2], af[mt], bf1 + 0);
                mma_f16(acc[mt][3], af[mt], bf1 + 2);
            }
        }
    }

    // ---- epilogue ----
#pragma unroll
    for (int mt = 0; mt < 4; ++mt) {
        const int r0 = row0 + wm * 64 + mt * 16 + g;
#pragma unroll
        for (int nt = 0; nt < 4; ++nt) {
            const int cb = col0 + wn * 32 + nt * 8 + 2 * c;
            float z[4];
            z[0] = acc[mt][nt][0] + __ldg(&bias[cb]);
            z[1] = acc[mt][nt][1] + __ldg(&bias[cb + 1]);
            z[2] = acc[mt][nt][2] + __ldg(&bias[cb]);
            z[3] = acc[mt][nt][3] + __ldg(&bias[cb + 1]);
            if (EPI == 0) {
                const float ga0 = __ldg(&gamma[cb]),     be0  = __ldg(&beta[cb]);
                const float ga1 = __ldg(&gamma[cb + 1]), be1v = __ldg(&beta[cb + 1]);
                z[0] = ga0 * fmaxf(z[0], 0.0f) * INV_BN + be0;
                z[1] = ga1 * fmaxf(z[1], 0.0f) * INV_BN + be1v;
                z[2] = ga0 * fmaxf(z[2], 0.0f) * INV_BN + be0;
                z[3] = ga1 * fmaxf(z[3], 0.0f) * INV_BN + be1v;
                __half* C = (__half*)Cv;
                *(__half2*)&C[(size_t)r0 * ldc + cb]       = __floats2half2_rn(z[0], z[1]);
                *(__half2*)&C[(size_t)(r0 + 8) * ldc + cb] = __floats2half2_rn(z[2], z[3]);
            } else {
                float* C = (float*)Cv;
                *(float2*)&C[(size_t)r0 * ldc + cb]       = make_float2(z[0], z[1]);
                *(float2*)&C[(size_t)(r0 + 8) * ldc + cb] = make_float2(z[2], z[3]);
            }
        }
    }
}

// ===========================================================================
// Prep kernels
// ===========================================================================
__global__ void pack_x_kernel(const float* __restrict__ x, __half* __restrict__ xe)
{
    const int i = blockIdx.x * 256 + threadIdx.x;   // over B_ROWS*64
    const int row = i >> 6, j = i & 63;
    xe[i] = __float2half_rn(x[(size_t)row * IN_DIM + 2 * j]);
}

// Transpose-pack: W[K][N] fp32 -> wp[N][K/2] uint32 {h(W[2kp][n]), h(W[2kp+1][n])}
// Tiled via smem; coalesced reads (over n) and writes (over kp).
__global__ void packT_w_kernel(const float* __restrict__ W, uint32_t* __restrict__ out,
                               int K2, int N)
{
    __shared__ uint32_t t[32][33];
    const int n0 = blockIdx.x * 32, kp0 = blockIdx.y * 32;
    const int x = threadIdx.x, y = threadIdx.y;    // 32 x 8
#pragma unroll
    for (int k = 0; k < 32; k += 8) {
        const int kp = kp0 + y + k;
        const __half lo = __float2half_rn(W[(size_t)(2 * kp)     * N + n0 + x]);
        const __half hi = __float2half_rn(W[(size_t)(2 * kp + 1) * N + n0 + x]);
        t[y + k][x] = (uint32_t)__half_as_ushort(lo)
                    | ((uint32_t)__half_as_ushort(hi) << 16);
    }
    __syncthreads();
#pragma unroll
    for (int k = 0; k < 32; k += 8)
        out[(size_t)(n0 + y + k) * K2 + kp0 + x] = t[x][y + k];
}

// ===========================================================================
// RQ-spline + scatter epilogue
// ===========================================================================
__global__ __launch_bounds__(256) void spline_kernel(
    const float* __restrict__ x,
    const float* __restrict__ params,
    float* __restrict__ out,
    float* __restrict__ logdet)
{
    const int tid = threadIdx.x;
    const int row = blockIdx.x * 4 + (tid >> 6);
    const int j = tid & 63;
    const float* p = params + (size_t)row * DOUT + j * 24;

    float wr[NBINS], hr[NBINS], drw[NBINS];
#pragma unroll
    for (int k = 0; k < NBINS; ++k) wr[k] = p[k];
#pragma unroll
    for (int k = 0; k < NBINS; ++k) hr[k] = p[NBINS + k];
#pragma unroll
    for (int k = 0; k < NBINS; ++k) drw[k] = p[2 * NBINS + k];

    const float xi = x[(size_t)row * IN_DIM + 2 * j + 1];
    const float xt = x[(size_t)row * IN_DIM + 2 * j];

    float cw[NBINS + 1], ch[NBINS + 1], dd[NBINS + 1];
    {
        float m = wr[0];
#pragma unroll
        for (int k = 1; k < NBINS; ++k) m = fmaxf(m, wr[k]);
        float e[NBINS], s = 0.0f;
#pragma unroll
        for (int k = 0; k < NBINS; ++k) { e[k] = expf(wr[k] - m); s += e[k]; }
        const float inv = 1.0f / s;
        cw[0] = 0.0f;
#pragma unroll
        for (int k = 0; k < NBINS; ++k)
            cw[k + 1] = cw[k] + (MIN_W + (1.0f - MIN_W * NBINS) * e[k] * inv);
    }
    {
        float m = hr[0];
#pragma unroll
        for (int k = 1; k < NBINS; ++k) m = fmaxf(m, hr[k]);
        float e[NBINS], s = 0.0f;
#pragma unroll
        for (int k = 0; k < NBINS; ++k) { e[k] = expf(hr[k] - m); s += e[k]; }
        const float inv = 1.0f / s;
        ch[0] = 0.0f;
#pragma unroll
        for (int k = 0; k < NBINS; ++k)
            ch[k + 1] = ch[k] + (MIN_H + (1.0f - MIN_H * NBINS) * e[k] * inv);
    }
#pragma unroll
    for (int k = 0; k < NBINS; ++k) {
        const float v = drw[k];
        dd[k] = MIN_D + (fmaxf(v, 0.0f) + log1pf(expf(-fabsf(v))));
    }
    dd[NBINS] = MIN_D;

    int bin = 0;
#pragma unroll
    for (int k = 0; k < NBINS; ++k) bin += (xi > cw[k]) ? 1 : 0;
    bin = min(max(bin, 0), NBINS - 1);

    const float xl = cw[bin], xr = cw[bin + 1];
    const float yl = ch[bin], yr = ch[bin + 1];
    const float bw = xr - xl, bh = yr - yl;
    const float dl = dd[bin], dr = dd[bin + 1];

    float t = (xi - xl) / bw;
    t = fminf(fmaxf(t, 0.0f), 1.0f);

    const float num = bh * (dl * t * t + 2.0f * t * (1.0f - t));
    const float den = dl + (dr - dl) * t;
    const float yv = yl + num / den;
    const float ld = logf(bh) + 2.0f * logf(2.0f * t * (1.0f - t) * dr + dl) - logf(den);

    out[(size_t)row * IN_DIM + 2 * j] = xt;
    out[(size_t)row * IN_DIM + 2 * j + 1] = yv;

    __shared__ float red[256];
    red[tid] = ld;
    __syncthreads();
    for (int s = 32; s > 0; s >>= 1) {
        if ((tid & 63) < s) red[tid] += red[tid + s];
        __syncthreads();
    }
    if ((tid & 63) == 0) logdet[row] = red[tid];
}

// ===========================================================================
// Host side
// ===========================================================================
extern "C" void kernel_launch(void* const* d_in, const int* in_sizes, int n_in,
                              void* d_out, int out_size)
{
    const float* x   = (const float*)d_in[0];
    const float* W1  = (const float*)d_in[1];
    const float* b1  = (const float*)d_in[2];
    const float* g1  = (const float*)d_in[3];
    const float* be1 = (const float*)d_in[4];
    const float* W2  = (const float*)d_in[5];
    const float* b2  = (const float*)d_in[6];
    const float* g2  = (const float*)d_in[7];
    const float* be2 = (const float*)d_in[8];
    const float* W3  = (const float*)d_in[9];
    const float* b3  = (const float*)d_in[10];

    float* out    = (float*)d_out;
    float* logdet = out + (size_t)B_ROWS * IN_DIM;

    __half *h1, *h2, *xe;
    float *pp;
    uint32_t *w1p, *w2p, *w3p;
    cudaGetSymbolAddress((void**)&h1,  g_h1);
    cudaGetSymbolAddress((void**)&h2,  g_h2);
    cudaGetSymbolAddress((void**)&pp,  g_params);
    cudaGetSymbolAddress((void**)&xe,  g_xe);
    cudaGetSymbolAddress((void**)&w1p, g_w1p);
    cudaGetSymbolAddress((void**)&w2p, g_w2p);
    cudaGetSymbolAddress((void**)&w3p, g_w3p);

    cudaFuncSetAttribute(mma_gemm_h<0>, cudaFuncAttributeMaxDynamicSharedMemorySize, SMEM_BYTES);
    cudaFuncSetAttribute(mma_gemm_h<1>, cudaFuncAttributeMaxDynamicSharedMemorySize, SMEM_BYTES);

    // Prep: pack x even cols + transpose-pack weights to n-major fp16 pairs
    pack_x_kernel<<<(B_ROWS * 64) / 256, 256>>>(x, xe);
    packT_w_kernel<<<dim3(HDIM / 32, 1),  dim3(32, 8)>>>(W1, w1p, 32,   HDIM);
    packT_w_kernel<<<dim3(HDIM / 32, 32), dim3(32, 8)>>>(W2, w2p, 1024, HDIM);
    packT_w_kernel<<<dim3(DOUT / 32, 32), dim3(32, 8)>>>(W3, w3p, 1024, DOUT);

    // GEMM1: [32768 x 64] @ [64 x 2048] -> h1 (fp16)
    mma_gemm_h<0><<<dim3(HDIM / 128, B_ROWS / 128), 256, SMEM_BYTES>>>(
        xe, 64, w1p, 32, h1, HDIM, 64, b1, g1, be1);
    // GEMM2: [32768 x 2048] @ [2048 x 2048] -> h2 (fp16)
    mma_gemm_h<0><<<dim3(HDIM / 128, B_ROWS / 128), 256, SMEM_BYTES>>>(
        h1, HDIM, w2p, 1024, h2, HDIM, HDIM, b2, g2, be2);
    // GEMM3: [32768 x 2048] @ [2048 x 1536] -> params (fp32)
    mma_gemm_h<1><<<dim3(DOUT / 128, B_ROWS / 128), 256, SMEM_BYTES>>>(
        h2, HDIM, w3p, 1024, pp, DOUT, HDIM, b3, (const float*)0, (const float*)0);

    // Spline + scatter + log_det
    spline_kernel<<<B_ROWS / 4, 256>>>(x, pp, out, logdet);
}